// round 16
// baseline (speedup 1.0000x reference)
#include <cuda_runtime.h>
#include <cuda_bf16.h>
#include <cstdint>
#include <math.h>

#define B_ 2
#define L_ 2048
#define H_ 8
#define E_ 64
#define D_ 64
#define NTILE 32

// ---------------- scratch ----------------
__device__ float g_sig[B_*H_*L_];
__device__ float g_coef[B_*H_*L_];
__device__ float g_i2s2[B_*H_*L_];

// pre-split bf16 copies, layout [bh][l][e] (128B rows). 6 x 4MB.
#define TEN_BYTES ((size_t)B_*H_*L_*E_*2)
#define QHI_O (0*TEN_BYTES)
#define QLO_O (1*TEN_BYTES)
#define KHI_O (2*TEN_BYTES)
#define KLO_O (3*TEN_BYTES)
#define VHI_O (4*TEN_BYTES)
#define VLO_O (5*TEN_BYTES)
__device__ __align__(128) char gsplit[6*(size_t)B_*H_*L_*E_*2];

__global__ void sigma_prep(const float* __restrict__ sigma) {
    int t = blockIdx.x * blockDim.x + threadIdx.x;
    if (t >= B_*H_*L_) return;
    int l  = t & (L_-1);
    int bh = t >> 11;
    int h  = bh & (H_-1);
    int b  = bh >> 3;
    float x  = sigma[((size_t)b*L_ + l)*H_ + h];
    float sgm = 1.f/(1.f + expf(-5.f*x));
    float sg  = sgm + 1e-5f;
    float p = powf(3.0f, sg);               // match XLA:GPU libdevice powf
    float s = p - 1.0f;
    g_sig[t]  = s;
    g_coef[t] = 0.3989422804014327f / s;
    g_i2s2[t] = 0.5f/(s*s);
}

__device__ __forceinline__ uint32_t bf2x(float a, float b) {
    __nv_bfloat162 t = __floats2bfloat162_rn(a, b);
    return *(uint32_t*)&t;
}
__device__ __forceinline__ float bflo(float x) {
    return x - __bfloat162float(__float2bfloat16_rn(x));
}

// one-shot: split Q (scaled), K, V into bf16 hi/lo, relaid [bh][l][e]
__global__ void split_prep(const float* __restrict__ Q, const float* __restrict__ K,
                           const float* __restrict__ V) {
    int t = blockIdx.x * blockDim.x + threadIdx.x;   // float4-group id
    if (t >= B_*H_*L_*E_/4) return;
    int e4 = t & 15;
    int h  = (t >> 4) & 7;
    int l  = (t >> 7) & 2047;
    int b  = t >> 18;
    size_t iin  = ((size_t)(b*L_ + l)*H_ + h)*(E_/4) + e4;
    size_t iout = ((size_t)((b*H_+h)*L_ + l))*(E_/4) + e4;

    float4 q = ((const float4*)Q)[iin];
    q.x *= 0.125f; q.y *= 0.125f; q.z *= 0.125f; q.w *= 0.125f;
    ((uint2*)(gsplit + QHI_O))[iout] = make_uint2(bf2x(q.x,q.y), bf2x(q.z,q.w));
    ((uint2*)(gsplit + QLO_O))[iout] = make_uint2(bf2x(bflo(q.x),bflo(q.y)), bf2x(bflo(q.z),bflo(q.w)));

    float4 k = ((const float4*)K)[iin];
    ((uint2*)(gsplit + KHI_O))[iout] = make_uint2(bf2x(k.x,k.y), bf2x(k.z,k.w));
    ((uint2*)(gsplit + KLO_O))[iout] = make_uint2(bf2x(bflo(k.x),bflo(k.y)), bf2x(bflo(k.z),bflo(k.w)));

    float4 v = ((const float4*)V)[iin];
    ((uint2*)(gsplit + VHI_O))[iout] = make_uint2(bf2x(v.x,v.y), bf2x(v.z,v.w));
    ((uint2*)(gsplit + VLO_O))[iout] = make_uint2(bf2x(bflo(v.x),bflo(v.y)), bf2x(bflo(v.z),bflo(v.w)));
}

// ---------------- helpers ----------------
__device__ __forceinline__ uint32_t smem_u32(const void* p) {
    uint32_t a;
    asm("{ .reg .u64 t; cvta.to.shared.u64 t, %1; cvt.u32.u64 %0, t; }" : "=r"(a) : "l"(p));
    return a;
}
#define LDSM_X4(r, a) \
    asm volatile("ldmatrix.sync.aligned.m8n8.x4.shared.b16 {%0,%1,%2,%3}, [%4];" \
        : "=r"((r)[0]),"=r"((r)[1]),"=r"((r)[2]),"=r"((r)[3]) : "r"(a))
#define LDSM_X4T(r, a) \
    asm volatile("ldmatrix.sync.aligned.m8n8.x4.trans.shared.b16 {%0,%1,%2,%3}, [%4];" \
        : "=r"((r)[0]),"=r"((r)[1]),"=r"((r)[2]),"=r"((r)[3]) : "r"(a))
#define MMA_BF16(d, a, b0, b1) \
    asm volatile("mma.sync.aligned.m16n8k16.row.col.f32.bf16.bf16.f32 " \
        "{%0,%1,%2,%3}, {%4,%5,%6,%7}, {%8,%9}, {%0,%1,%2,%3};" \
        : "+f"((d)[0]),"+f"((d)[1]),"+f"((d)[2]),"+f"((d)[3]) \
        : "r"((a)[0]),"r"((a)[1]),"r"((a)[2]),"r"((a)[3]), "r"(b0),"r"(b1))

__device__ __forceinline__ void cp16(uint32_t dst, const void* src) {
    asm volatile("cp.async.ca.shared.global [%0], [%1], 16;" :: "r"(dst), "l"(src));
}
#define CP_WAIT_ALL() asm volatile("cp.async.commit_group;\n\tcp.async.wait_group 0;" ::: "memory")

__device__ __forceinline__ uint32_t swrel(int row, int c16) {
    uint32_t off = (uint32_t)(row*128 + c16*16);
    return off ^ ((off >> 3) & 0x70);
}
__device__ __forceinline__ float2 bfup(uint32_t u) {
    return __bfloat1622float2(*(__nv_bfloat162*)&u);
}

// smem map (bytes)
#define SM_PQHI 0            // Q hi, then P hi (overlay after frag hoist)
#define SM_PQLO 8192
#define SM_KHI  16384
#define SM_KLO  24576
#define SM_VHI  32768
#define SM_VLO  40960
#define SM_RLP  49152        // rlpart[2][64] fp32
#define SM_TOTAL (SM_RLP + 512)

__global__ __launch_bounds__(256, 2)
void attn_tc(float* __restrict__ out)
{
    extern __shared__ char smc[];
    const uint32_t sb = smem_u32(smc);
    float* rlp = (float*)(smc + SM_RLP);   // [2][64]

    const int tx  = threadIdx.x;
    const int lid = tx & 31;
    const int wid = tx >> 5;
    const int wm  = wid & 3;
    const int wn  = wid >> 2;

    // LPT grid: largest row-tiles dispatched first; bh fastest
    const int bh = blockIdx.x;             // 0..15
    const int it = (NTILE-1) - blockIdx.y; // 31..0
    const int b  = bh >> 3;
    const int h  = bh & (H_-1);
    const int i0 = it * 64;
    const int jlim = it + 1;

    float* outV = out;
    float* outS = out + (size_t)B_*L_*H_*D_;
    float* outP = outS + (size_t)B_*H_*L_*L_;
    float* outG = outP + (size_t)B_*H_*L_*L_;

    const int a_row = wm*16 + (lid & 7) + ((lid >> 3) & 1)*8;
    const int a_c16 = (lid >> 4);
    const int bk_row = (lid & 7) + (lid >> 4)*8;
    const int bk_c16 = ((lid >> 3) & 1);
    const int bv_row = (lid & 7) + ((lid >> 3) & 1)*8;
    const int bv_c16 = wn*4 + (lid >> 4);

    const int srow = tx >> 4;
    const int sc0  = (tx & 15)*4;

    // cp.async chunk mapping: 512 chunks per 8KB array, 2 per thread
    const int ch_row0 = tx >> 3,        ch_c160 = tx & 7;
    const int ch_row1 = (tx+256) >> 3,  ch_c161 = (tx+256) & 7;
    const uint32_t chrel0 = swrel(ch_row0, ch_c160);
    const uint32_t chrel1 = swrel(ch_row1, ch_c161);
    const size_t  choff0 = (size_t)ch_row0*128 + ch_c160*16;
    const size_t  choff1 = (size_t)ch_row1*128 + ch_c161*16;

    const int fr0 = wm*16 + (lid >> 2);
    const int fr1 = fr0 + 8;
    const int fcb = wn*32 + (lid & 3)*2;

    float coef4[4], i2s24[4], sig4[4];
    #pragma unroll
    for (int p = 0; p < 4; p++) {
        int gi = bh*L_ + i0 + srow + p*16;
        coef4[p] = g_coef[gi]; i2s24[p] = g_i2s2[gi]; sig4[p] = g_sig[gi];
    }

    // ---- Q tile: cp.async pre-split bf16 into PQ region ----
    {
        const char* srch = gsplit + QHI_O + ((size_t)(bh*L_ + i0))*128;
        const char* srcl = gsplit + QLO_O + ((size_t)(bh*L_ + i0))*128;
        cp16(sb + SM_PQHI + chrel0, srch + choff0);
        cp16(sb + SM_PQHI + chrel1, srch + choff1);
        cp16(sb + SM_PQLO + chrel0, srcl + choff0);
        cp16(sb + SM_PQLO + chrel1, srcl + choff1);
        CP_WAIT_ALL();
    }
    __syncthreads();

    // ---- hoist Q fragments (j-invariant) ----
    uint32_t qh[4][4], ql[4][4];
    #pragma unroll
    for (int kc = 0; kc < 4; kc++) {
        LDSM_X4(qh[kc], sb + SM_PQHI + swrel(a_row, a_c16 + kc*2));
        LDSM_X4(ql[kc], sb + SM_PQLO + swrel(a_row, a_c16 + kc*2));
    }

    // non-causal tiles interleaved into pass A: per iteration quota
    const int nonc = NTILE - jlim;
    const int per = (nonc + jlim - 1) / jlim;   // ceil; 0 when nonc==0
    int jnc = jlim;                              // next non-causal tile to store

    // ================= PASS A: row sums + interleaved non-causal stores =================
    float rp0 = 0.f, rp1 = 0.f;
    #pragma unroll 1
    for (int jt = 0; jt < jlim; jt++) {
        const int j0 = jt*64;
        __syncthreads();
        {
            const char* kh = gsplit + KHI_O + ((size_t)(bh*L_ + j0))*128;
            const char* kl = gsplit + KLO_O + ((size_t)(bh*L_ + j0))*128;
            cp16(sb + SM_KHI + chrel0, kh + choff0);
            cp16(sb + SM_KHI + chrel1, kh + choff1);
            cp16(sb + SM_KLO + chrel0, kl + choff0);
            cp16(sb + SM_KLO + chrel1, kl + choff1);
            CP_WAIT_ALL();
        }
        __syncthreads();

        float sacc[4][4] = {};
        #pragma unroll
        for (int kc = 0; kc < 4; kc++) {
            uint32_t bh0[4], bh1[4], bl0[4], bl1[4];
            LDSM_X4(bh0, sb + SM_KHI + swrel(wn*32 + bk_row,      bk_c16 + kc*2));
            LDSM_X4(bh1, sb + SM_KHI + swrel(wn*32 + 16 + bk_row, bk_c16 + kc*2));
            LDSM_X4(bl0, sb + SM_KLO + swrel(wn*32 + bk_row,      bk_c16 + kc*2));
            LDSM_X4(bl1, sb + SM_KLO + swrel(wn*32 + 16 + bk_row, bk_c16 + kc*2));
            #pragma unroll
            for (int nt = 0; nt < 4; nt++) {
                const uint32_t* BH = (nt < 2) ? bh0 : bh1;
                const uint32_t* BL = (nt < 2) ? bl0 : bl1;
                int u = (nt & 1)*2;
                MMA_BF16(sacc[nt], qh[kc], BH[u], BH[u+1]);
                MMA_BF16(sacc[nt], qh[kc], BL[u], BL[u+1]);
                MMA_BF16(sacc[nt], ql[kc], BH[u], BH[u+1]);
            }
        }
        #pragma unroll
        for (int nt = 0; nt < 4; nt++) {
            int col = fcb + nt*8;
            rp0 += ((j0+col   > i0+fr0) ? 0.f : __expf(sacc[nt][0]))
                 + ((j0+col+1 > i0+fr0) ? 0.f : __expf(sacc[nt][1]));
            rp1 += ((j0+col   > i0+fr1) ? 0.f : __expf(sacc[nt][2]))
                 + ((j0+col+1 > i0+fr1) ? 0.f : __expf(sacc[nt][3]));
        }

        // ---- interleaved non-causal stores (zero series + prior + sigma) ----
        #pragma unroll 1
        for (int q = 0; q < per && jnc < NTILE; q++, jnc++) {
            const int jn0 = jnc*64;
            const float4 z = make_float4(0.f,0.f,0.f,0.f);
            #pragma unroll
            for (int p = 0; p < 4; p++) {
                int irow = i0 + srow + p*16;
                size_t off = ((size_t)bh*L_ + irow)*L_ + jn0 + sc0;
                float vals[4];
                #pragma unroll
                for (int c = 0; c < 4; c++) {
                    int d = irow - (jn0 + sc0 + c);
                    float arg = -(float)(d*d) * i2s24[p];
                    vals[c] = (arg > -87.f) ? (coef4[p] * __expf(arg)) : 0.f;
                }
                __stcs((float4*)(outS + off), z);
                __stcs((float4*)(outP + off), make_float4(vals[0],vals[1],vals[2],vals[3]));
                __stcs((float4*)(outG + off), make_float4(sig4[p],sig4[p],sig4[p],sig4[p]));
            }
        }
    }
    // deterministic cross-lane + cross-warp reduction
    rp0 += __shfl_xor_sync(0xffffffffu, rp0, 1);
    rp0 += __shfl_xor_sync(0xffffffffu, rp0, 2);
    rp1 += __shfl_xor_sync(0xffffffffu, rp1, 1);
    rp1 += __shfl_xor_sync(0xffffffffu, rp1, 2);
    if ((lid & 3) == 0) {
        rlp[wn*64 + fr0] = rp0;
        rlp[wn*64 + fr1] = rp1;
    }
    __syncthreads();
    const float rlr0 = 1.f / (rlp[fr0] + rlp[64 + fr0]);
    const float rlr1 = 1.f / (rlp[fr1] + rlp[64 + fr1]);

    // ================= PASS B: normalized series + PV + prior/sigma =================
    float oacc[4][4] = {};
    #pragma unroll 1
    for (int jt = 0; jt < jlim; jt++) {
        const int j0 = jt*64;
        __syncthreads();
        {
            const char* kh = gsplit + KHI_O + ((size_t)(bh*L_ + j0))*128;
            const char* kl = gsplit + KLO_O + ((size_t)(bh*L_ + j0))*128;
            const char* vh = gsplit + VHI_O + ((size_t)(bh*L_ + j0))*128;
            const char* vl = gsplit + VLO_O + ((size_t)(bh*L_ + j0))*128;
            cp16(sb + SM_KHI + chrel0, kh + choff0);
            cp16(sb + SM_KHI + chrel1, kh + choff1);
            cp16(sb + SM_KLO + chrel0, kl + choff0);
            cp16(sb + SM_KLO + chrel1, kl + choff1);
            cp16(sb + SM_VHI + chrel0, vh + choff0);
            cp16(sb + SM_VHI + chrel1, vh + choff1);
            cp16(sb + SM_VLO + chrel0, vl + choff0);
            cp16(sb + SM_VLO + chrel1, vl + choff1);
            CP_WAIT_ALL();
        }
        __syncthreads();

        float sacc[4][4] = {};
        #pragma unroll
        for (int kc = 0; kc < 4; kc++) {
            uint32_t bh0[4], bh1[4], bl0[4], bl1[4];
            LDSM_X4(bh0, sb + SM_KHI + swrel(wn*32 + bk_row,      bk_c16 + kc*2));
            LDSM_X4(bh1, sb + SM_KHI + swrel(wn*32 + 16 + bk_row, bk_c16 + kc*2));
            LDSM_X4(bl0, sb + SM_KLO + swrel(wn*32 + bk_row,      bk_c16 + kc*2));
            LDSM_X4(bl1, sb + SM_KLO + swrel(wn*32 + 16 + bk_row, bk_c16 + kc*2));
            #pragma unroll
            for (int nt = 0; nt < 4; nt++) {
                const uint32_t* BH = (nt < 2) ? bh0 : bh1;
                const uint32_t* BL = (nt < 2) ? bl0 : bl1;
                int u = (nt & 1)*2;
                MMA_BF16(sacc[nt], qh[kc], BH[u], BH[u+1]);
                MMA_BF16(sacc[nt], qh[kc], BL[u], BL[u+1]);
                MMA_BF16(sacc[nt], ql[kc], BH[u], BH[u+1]);
            }
        }

        // exp * rl -> normalized split P into PQ region
        #pragma unroll
        for (int nt = 0; nt < 4; nt++) {
            int col = fcb + nt*8;
            float p0 = (j0+col   > i0+fr0) ? 0.f : __expf(sacc[nt][0])*rlr0;
            float p1 = (j0+col+1 > i0+fr0) ? 0.f : __expf(sacc[nt][1])*rlr0;
            float p2 = (j0+col   > i0+fr1) ? 0.f : __expf(sacc[nt][2])*rlr1;
            float p3 = (j0+col+1 > i0+fr1) ? 0.f : __expf(sacc[nt][3])*rlr1;
            uint32_t rel0 = swrel(fr0, (col*2) >> 4) + ((col*2) & 15);
            uint32_t rel1 = swrel(fr1, (col*2) >> 4) + ((col*2) & 15);
            *(uint32_t*)(smc + SM_PQHI + rel0) = bf2x(p0, p1);
            *(uint32_t*)(smc + SM_PQLO + rel0) = bf2x(bflo(p0), bflo(p1));
            *(uint32_t*)(smc + SM_PQHI + rel1) = bf2x(p2, p3);
            *(uint32_t*)(smc + SM_PQLO + rel1) = bf2x(bflo(p2), bflo(p3));
        }
        __syncthreads();

        // O += P V (3 split passes)
        #pragma unroll
        for (int kc = 0; kc < 4; kc++) {
            uint32_t ah[4], al[4], bh2[4], bl2[4], bh3[4], bl3[4];
            LDSM_X4(ah, sb + SM_PQHI + swrel(a_row, a_c16 + kc*2));
            LDSM_X4(al, sb + SM_PQLO + swrel(a_row, a_c16 + kc*2));
            LDSM_X4T(bh2, sb + SM_VHI + swrel(kc*16 + bv_row, bv_c16));
            LDSM_X4T(bl2, sb + SM_VLO + swrel(kc*16 + bv_row, bv_c16));
            LDSM_X4T(bh3, sb + SM_VHI + swrel(kc*16 + bv_row, bv_c16 + 2));
            LDSM_X4T(bl3, sb + SM_VLO + swrel(kc*16 + bv_row, bv_c16 + 2));
            #pragma unroll
            for (int nt = 0; nt < 4; nt++) {
                const uint32_t* BH = (nt < 2) ? bh2 : bh3;
                const uint32_t* BL = (nt < 2) ? bl2 : bl3;
                int u = (nt & 1)*2;
                MMA_BF16(oacc[nt], ah, BH[u], BH[u+1]);
                MMA_BF16(oacc[nt], ah, BL[u], BL[u+1]);
                MMA_BF16(oacc[nt], al, BH[u], BH[u+1]);
            }
        }

        // series (already normalized) + prior + sigma, streaming stores
        #pragma unroll
        for (int p = 0; p < 4; p++) {
            int rloc = srow + p*16;
            int irow = i0 + rloc;
            size_t off = ((size_t)bh*L_ + irow)*L_ + j0 + sc0;
            uint32_t rel = swrel(rloc, (sc0*2) >> 4) + ((sc0*2) & 15);
            uint2 hv = *(const uint2*)(smc + SM_PQHI + rel);
            uint2 lv = *(const uint2*)(smc + SM_PQLO + rel);
            float2 ha = bfup(hv.x), hb2 = bfup(hv.y);
            float2 la = bfup(lv.x), lb2 = bfup(lv.y);
            __stcs((float4*)(outS + off),
                   make_float4(ha.x+la.x, ha.y+la.y, hb2.x+lb2.x, hb2.y+lb2.y));
            float vals[4];
            #pragma unroll
            for (int c = 0; c < 4; c++) {
                int d = irow - (j0 + sc0 + c);
                float arg = -(float)(d*d) * i2s24[p];
                vals[c] = (arg > -87.f) ? (coef4[p] * __expf(arg)) : 0.f;
            }
            __stcs((float4*)(outP + off), make_float4(vals[0],vals[1],vals[2],vals[3]));
            __stcs((float4*)(outG + off), make_float4(sig4[p],sig4[p],sig4[p],sig4[p]));
        }
    }

    // ---- V output (already normalized) ----
    {
        float* v0 = outV + (((size_t)(b*L_) + i0 + fr0)*H_ + h)*D_;
        float* v1 = outV + (((size_t)(b*L_) + i0 + fr1)*H_ + h)*D_;
        #pragma unroll
        for (int nt = 0; nt < 4; nt++) {
            int col = fcb + nt*8;
            __stcs((float2*)(v0 + col), make_float2(oacc[nt][0], oacc[nt][1]));
            __stcs((float2*)(v1 + col), make_float2(oacc[nt][2], oacc[nt][3]));
        }
    }
}

extern "C" void kernel_launch(void* const* d_in, const int* in_sizes, int n_in,
                              void* d_out, int out_size) {
    const float* q  = (const float*)d_in[0];
    const float* k  = (const float*)d_in[1];
    const float* v  = (const float*)d_in[2];
    const float* sg = (const float*)d_in[3];

    sigma_prep<<<(B_*H_*L_ + 255)/256, 256>>>(sg);
    split_prep<<<(B_*H_*L_*E_/4 + 255)/256, 256>>>(q, k, v);

    cudaFuncSetAttribute(attn_tc, cudaFuncAttributeMaxDynamicSharedMemorySize, SM_TOTAL);
    dim3 grid(B_*H_, NTILE);   // bh fastest; it = 31 - blockIdx.y (LPT)
    attn_tc<<<grid, 256, SM_TOTAL>>>((float*)d_out);
}

// round 17
// speedup vs baseline: 1.0481x; 1.0481x over previous
#include <cuda_runtime.h>
#include <cuda_bf16.h>
#include <cstdint>
#include <math.h>

#define B_ 2
#define L_ 2048
#define H_ 8
#define E_ 64
#define D_ 64
#define NTILE 32

// ---------------- scratch ----------------
__device__ float g_sig[B_*H_*L_];
__device__ float g_coef[B_*H_*L_];
__device__ float g_i2s2[B_*H_*L_];

// pre-split bf16 copies, layout [bh][l][e] (128B rows). 6 x 4MB.
#define TEN_BYTES ((size_t)B_*H_*L_*E_*2)
#define QHI_O (0*TEN_BYTES)
#define QLO_O (1*TEN_BYTES)
#define KHI_O (2*TEN_BYTES)
#define KLO_O (3*TEN_BYTES)
#define VHI_O (4*TEN_BYTES)
#define VLO_O (5*TEN_BYTES)
__device__ __align__(128) char gsplit[6*(size_t)B_*H_*L_*E_*2];

__global__ void sigma_prep(const float* __restrict__ sigma) {
    int t = blockIdx.x * blockDim.x + threadIdx.x;
    if (t >= B_*H_*L_) return;
    int l  = t & (L_-1);
    int bh = t >> 11;
    int h  = bh & (H_-1);
    int b  = bh >> 3;
    float x  = sigma[((size_t)b*L_ + l)*H_ + h];
    float sgm = 1.f/(1.f + expf(-5.f*x));
    float sg  = sgm + 1e-5f;
    float p = powf(3.0f, sg);               // match XLA:GPU libdevice powf
    float s = p - 1.0f;
    g_sig[t]  = s;
    g_coef[t] = 0.3989422804014327f / s;
    g_i2s2[t] = 0.5f/(s*s);
}

__device__ __forceinline__ uint32_t bf2x(float a, float b) {
    __nv_bfloat162 t = __floats2bfloat162_rn(a, b);
    return *(uint32_t*)&t;
}
__device__ __forceinline__ float bflo(float x) {
    return x - __bfloat162float(__float2bfloat16_rn(x));
}

// one-shot: split Q (scaled), K, V into bf16 hi/lo, relaid [bh][l][e]
__global__ void split_prep(const float* __restrict__ Q, const float* __restrict__ K,
                           const float* __restrict__ V) {
    int t = blockIdx.x * blockDim.x + threadIdx.x;   // float4-group id
    if (t >= B_*H_*L_*E_/4) return;
    int e4 = t & 15;
    int h  = (t >> 4) & 7;
    int l  = (t >> 7) & 2047;
    int b  = t >> 18;
    size_t iin  = ((size_t)(b*L_ + l)*H_ + h)*(E_/4) + e4;
    size_t iout = ((size_t)((b*H_+h)*L_ + l))*(E_/4) + e4;

    float4 q = ((const float4*)Q)[iin];
    q.x *= 0.125f; q.y *= 0.125f; q.z *= 0.125f; q.w *= 0.125f;
    ((uint2*)(gsplit + QHI_O))[iout] = make_uint2(bf2x(q.x,q.y), bf2x(q.z,q.w));
    ((uint2*)(gsplit + QLO_O))[iout] = make_uint2(bf2x(bflo(q.x),bflo(q.y)), bf2x(bflo(q.z),bflo(q.w)));

    float4 k = ((const float4*)K)[iin];
    ((uint2*)(gsplit + KHI_O))[iout] = make_uint2(bf2x(k.x,k.y), bf2x(k.z,k.w));
    ((uint2*)(gsplit + KLO_O))[iout] = make_uint2(bf2x(bflo(k.x),bflo(k.y)), bf2x(bflo(k.z),bflo(k.w)));

    float4 v = ((const float4*)V)[iin];
    ((uint2*)(gsplit + VHI_O))[iout] = make_uint2(bf2x(v.x,v.y), bf2x(v.z,v.w));
    ((uint2*)(gsplit + VLO_O))[iout] = make_uint2(bf2x(bflo(v.x),bflo(v.y)), bf2x(bflo(v.z),bflo(v.w)));
}

// ---------------- helpers ----------------
__device__ __forceinline__ uint32_t smem_u32(const void* p) {
    uint32_t a;
    asm("{ .reg .u64 t; cvta.to.shared.u64 t, %1; cvt.u32.u64 %0, t; }" : "=r"(a) : "l"(p));
    return a;
}
#define LDSM_X4(r, a) \
    asm volatile("ldmatrix.sync.aligned.m8n8.x4.shared.b16 {%0,%1,%2,%3}, [%4];" \
        : "=r"((r)[0]),"=r"((r)[1]),"=r"((r)[2]),"=r"((r)[3]) : "r"(a))
#define LDSM_X4T(r, a) \
    asm volatile("ldmatrix.sync.aligned.m8n8.x4.trans.shared.b16 {%0,%1,%2,%3}, [%4];" \
        : "=r"((r)[0]),"=r"((r)[1]),"=r"((r)[2]),"=r"((r)[3]) : "r"(a))
#define MMA_BF16(d, a, b0, b1) \
    asm volatile("mma.sync.aligned.m16n8k16.row.col.f32.bf16.bf16.f32 " \
        "{%0,%1,%2,%3}, {%4,%5,%6,%7}, {%8,%9}, {%0,%1,%2,%3};" \
        : "+f"((d)[0]),"+f"((d)[1]),"+f"((d)[2]),"+f"((d)[3]) \
        : "r"((a)[0]),"r"((a)[1]),"r"((a)[2]),"r"((a)[3]), "r"(b0),"r"(b1))

__device__ __forceinline__ void cp16(uint32_t dst, const void* src) {
    asm volatile("cp.async.ca.shared.global [%0], [%1], 16;" :: "r"(dst), "l"(src));
}
#define CP_WAIT_ALL() asm volatile("cp.async.commit_group;\n\tcp.async.wait_group 0;" ::: "memory")

__device__ __forceinline__ uint32_t swrel(int row, int c16) {
    uint32_t off = (uint32_t)(row*128 + c16*16);
    return off ^ ((off >> 3) & 0x70);
}
__device__ __forceinline__ float2 bfup(uint32_t u) {
    return __bfloat1622float2(*(__nv_bfloat162*)&u);
}

// smem map (bytes)
#define SM_PQHI 0            // Q hi, then P hi (overlay after frag hoist)
#define SM_PQLO 8192
#define SM_KHI  16384
#define SM_KLO  24576
#define SM_VHI  32768
#define SM_VLO  40960
#define SM_RLP  49152        // rlpart[2][64] fp32
#define SM_TOTAL (SM_RLP + 512)

__global__ __launch_bounds__(256, 2)
void attn_tc(float* __restrict__ out)
{
    extern __shared__ char smc[];
    const uint32_t sb = smem_u32(smc);
    float* rlp = (float*)(smc + SM_RLP);   // [2][64]

    const int tx  = threadIdx.x;
    const int lid = tx & 31;
    const int wid = tx >> 5;
    const int wm  = wid & 3;
    const int wn  = wid >> 2;

    // LPT grid: largest row-tiles dispatched first; bh fastest
    const int bh = blockIdx.x;             // 0..15
    const int it = (NTILE-1) - blockIdx.y; // 31..0
    const int b  = bh >> 3;
    const int h  = bh & (H_-1);
    const int i0 = it * 64;
    const int jlim = it + 1;

    float* outV = out;
    float* outS = out + (size_t)B_*L_*H_*D_;
    float* outP = outS + (size_t)B_*H_*L_*L_;
    float* outG = outP + (size_t)B_*H_*L_*L_;

    const int a_row = wm*16 + (lid & 7) + ((lid >> 3) & 1)*8;
    const int a_c16 = (lid >> 4);
    const int bk_row = (lid & 7) + (lid >> 4)*8;
    const int bk_c16 = ((lid >> 3) & 1);
    const int bv_row = (lid & 7) + ((lid >> 3) & 1)*8;
    const int bv_c16 = wn*4 + (lid >> 4);

    const int srow = tx >> 4;
    const int sc0  = (tx & 15)*4;

    // cp.async chunk mapping: 512 chunks per 8KB array, 2 per thread
    const int ch_row0 = tx >> 3,        ch_c160 = tx & 7;
    const int ch_row1 = (tx+256) >> 3,  ch_c161 = (tx+256) & 7;
    const uint32_t chrel0 = swrel(ch_row0, ch_c160);
    const uint32_t chrel1 = swrel(ch_row1, ch_c161);
    const size_t  choff0 = (size_t)ch_row0*128 + ch_c160*16;
    const size_t  choff1 = (size_t)ch_row1*128 + ch_c161*16;

    const int fr0 = wm*16 + (lid >> 2);
    const int fr1 = fr0 + 8;
    const int fcb = wn*32 + (lid & 3)*2;

    float coef4[4], i2s24[4], sig4[4];
    #pragma unroll
    for (int p = 0; p < 4; p++) {
        int gi = bh*L_ + i0 + srow + p*16;
        coef4[p] = g_coef[gi]; i2s24[p] = g_i2s2[gi]; sig4[p] = g_sig[gi];
    }

    // ---- Q tile: cp.async pre-split bf16 into PQ region ----
    {
        const char* srch = gsplit + QHI_O + ((size_t)(bh*L_ + i0))*128;
        const char* srcl = gsplit + QLO_O + ((size_t)(bh*L_ + i0))*128;
        cp16(sb + SM_PQHI + chrel0, srch + choff0);
        cp16(sb + SM_PQHI + chrel1, srch + choff1);
        cp16(sb + SM_PQLO + chrel0, srcl + choff0);
        cp16(sb + SM_PQLO + chrel1, srcl + choff1);
        CP_WAIT_ALL();
    }
    __syncthreads();

    // ---- hoist Q fragments (j-invariant) ----
    uint32_t qh[4][4], ql[4][4];
    #pragma unroll
    for (int kc = 0; kc < 4; kc++) {
        LDSM_X4(qh[kc], sb + SM_PQHI + swrel(a_row, a_c16 + kc*2));
        LDSM_X4(ql[kc], sb + SM_PQLO + swrel(a_row, a_c16 + kc*2));
    }

    // non-causal tiles interleaved into pass A: per iteration quota
    const int nonc = NTILE - jlim;
    const int per = (nonc + jlim - 1) / jlim;   // ceil; 0 when nonc==0
    int jnc = jlim;                              // next non-causal tile to store

    // ================= PASS A: row sums + interleaved non-causal stores =================
    float rp0 = 0.f, rp1 = 0.f;
    #pragma unroll 1
    for (int jt = 0; jt < jlim; jt++) {
        const int j0 = jt*64;
        __syncthreads();
        {
            const char* kh = gsplit + KHI_O + ((size_t)(bh*L_ + j0))*128;
            const char* kl = gsplit + KLO_O + ((size_t)(bh*L_ + j0))*128;
            cp16(sb + SM_KHI + chrel0, kh + choff0);
            cp16(sb + SM_KHI + chrel1, kh + choff1);
            cp16(sb + SM_KLO + chrel0, kl + choff0);
            cp16(sb + SM_KLO + chrel1, kl + choff1);
            CP_WAIT_ALL();
        }
        __syncthreads();

        float sacc[4][4] = {};
        #pragma unroll
        for (int kc = 0; kc < 4; kc++) {
            uint32_t bh0[4], bh1[4], bl0[4], bl1[4];
            LDSM_X4(bh0, sb + SM_KHI + swrel(wn*32 + bk_row,      bk_c16 + kc*2));
            LDSM_X4(bh1, sb + SM_KHI + swrel(wn*32 + 16 + bk_row, bk_c16 + kc*2));
            LDSM_X4(bl0, sb + SM_KLO + swrel(wn*32 + bk_row,      bk_c16 + kc*2));
            LDSM_X4(bl1, sb + SM_KLO + swrel(wn*32 + 16 + bk_row, bk_c16 + kc*2));
            #pragma unroll
            for (int nt = 0; nt < 4; nt++) {
                const uint32_t* BH = (nt < 2) ? bh0 : bh1;
                const uint32_t* BL = (nt < 2) ? bl0 : bl1;
                int u = (nt & 1)*2;
                MMA_BF16(sacc[nt], qh[kc], BH[u], BH[u+1]);
                MMA_BF16(sacc[nt], qh[kc], BL[u], BL[u+1]);
                MMA_BF16(sacc[nt], ql[kc], BH[u], BH[u+1]);
            }
        }
        #pragma unroll
        for (int nt = 0; nt < 4; nt++) {
            int col = fcb + nt*8;
            rp0 += ((j0+col   > i0+fr0) ? 0.f : __expf(sacc[nt][0]))
                 + ((j0+col+1 > i0+fr0) ? 0.f : __expf(sacc[nt][1]));
            rp1 += ((j0+col   > i0+fr1) ? 0.f : __expf(sacc[nt][2]))
                 + ((j0+col+1 > i0+fr1) ? 0.f : __expf(sacc[nt][3]));
        }

        // ---- interleaved non-causal stores (zero series + prior + sigma) ----
        #pragma unroll 1
        for (int q = 0; q < per && jnc < NTILE; q++, jnc++) {
            const int jn0 = jnc*64;
            const float4 z = make_float4(0.f,0.f,0.f,0.f);
            #pragma unroll
            for (int p = 0; p < 4; p++) {
                int irow = i0 + srow + p*16;
                size_t off = ((size_t)bh*L_ + irow)*L_ + jn0 + sc0;
                // tile-strip underflow fast path: closest column gives max arg
                int dmin = jn0 + sc0 > irow ? (jn0 + sc0 - irow) : 0;   // non-causal: jn0 >= irow-... but sc0 cols
                // (for non-causal tiles jn0 > irow always except partial; compute generally)
                int dfar = irow - (jn0 + sc0 + 3);
                if (dfar > dmin) dmin = dfar;
                if (dmin < 0) dmin = 0;
                float dmin2 = (float)(dmin*dmin);
                if (dmin2 * i2s24[p] > 87.f) {
                    __stcs((float4*)(outS + off), z);
                    __stcs((float4*)(outP + off), z);
                    __stcs((float4*)(outG + off), make_float4(sig4[p],sig4[p],sig4[p],sig4[p]));
                } else {
                    float vals[4];
                    #pragma unroll
                    for (int c = 0; c < 4; c++) {
                        int d = irow - (jn0 + sc0 + c);
                        float arg = -(float)(d*d) * i2s24[p];
                        vals[c] = (arg > -87.f) ? (coef4[p] * __expf(arg)) : 0.f;
                    }
                    __stcs((float4*)(outS + off), z);
                    __stcs((float4*)(outP + off), make_float4(vals[0],vals[1],vals[2],vals[3]));
                    __stcs((float4*)(outG + off), make_float4(sig4[p],sig4[p],sig4[p],sig4[p]));
                }
            }
        }
    }
    // deterministic cross-lane + cross-warp reduction
    rp0 += __shfl_xor_sync(0xffffffffu, rp0, 1);
    rp0 += __shfl_xor_sync(0xffffffffu, rp0, 2);
    rp1 += __shfl_xor_sync(0xffffffffu, rp1, 1);
    rp1 += __shfl_xor_sync(0xffffffffu, rp1, 2);
    if ((lid & 3) == 0) {
        rlp[wn*64 + fr0] = rp0;
        rlp[wn*64 + fr1] = rp1;
    }
    __syncthreads();
    const float rlr0 = 1.f / (rlp[fr0] + rlp[64 + fr0]);
    const float rlr1 = 1.f / (rlp[fr1] + rlp[64 + fr1]);

    // ================= PASS B: normalized series + PV + prior/sigma =================
    float oacc[4][4] = {};
    #pragma unroll 1
    for (int jt = 0; jt < jlim; jt++) {
        const int j0 = jt*64;
        __syncthreads();
        {
            const char* kh = gsplit + KHI_O + ((size_t)(bh*L_ + j0))*128;
            const char* kl = gsplit + KLO_O + ((size_t)(bh*L_ + j0))*128;
            const char* vh = gsplit + VHI_O + ((size_t)(bh*L_ + j0))*128;
            const char* vl = gsplit + VLO_O + ((size_t)(bh*L_ + j0))*128;
            cp16(sb + SM_KHI + chrel0, kh + choff0);
            cp16(sb + SM_KHI + chrel1, kh + choff1);
            cp16(sb + SM_KLO + chrel0, kl + choff0);
            cp16(sb + SM_KLO + chrel1, kl + choff1);
            cp16(sb + SM_VHI + chrel0, vh + choff0);
            cp16(sb + SM_VHI + chrel1, vh + choff1);
            cp16(sb + SM_VLO + chrel0, vl + choff0);
            cp16(sb + SM_VLO + chrel1, vl + choff1);
            CP_WAIT_ALL();
        }
        __syncthreads();

        float sacc[4][4] = {};
        #pragma unroll
        for (int kc = 0; kc < 4; kc++) {
            uint32_t bh0[4], bh1[4], bl0[4], bl1[4];
            LDSM_X4(bh0, sb + SM_KHI + swrel(wn*32 + bk_row,      bk_c16 + kc*2));
            LDSM_X4(bh1, sb + SM_KHI + swrel(wn*32 + 16 + bk_row, bk_c16 + kc*2));
            LDSM_X4(bl0, sb + SM_KLO + swrel(wn*32 + bk_row,      bk_c16 + kc*2));
            LDSM_X4(bl1, sb + SM_KLO + swrel(wn*32 + 16 + bk_row, bk_c16 + kc*2));
            #pragma unroll
            for (int nt = 0; nt < 4; nt++) {
                const uint32_t* BH = (nt < 2) ? bh0 : bh1;
                const uint32_t* BL = (nt < 2) ? bl0 : bl1;
                int u = (nt & 1)*2;
                MMA_BF16(sacc[nt], qh[kc], BH[u], BH[u+1]);
                MMA_BF16(sacc[nt], qh[kc], BL[u], BL[u+1]);
                MMA_BF16(sacc[nt], ql[kc], BH[u], BH[u+1]);
            }
        }

        // exp * rl -> normalized split P into PQ region
        #pragma unroll
        for (int nt = 0; nt < 4; nt++) {
            int col = fcb + nt*8;
            float p0 = (j0+col   > i0+fr0) ? 0.f : __expf(sacc[nt][0])*rlr0;
            float p1 = (j0+col+1 > i0+fr0) ? 0.f : __expf(sacc[nt][1])*rlr0;
            float p2 = (j0+col   > i0+fr1) ? 0.f : __expf(sacc[nt][2])*rlr1;
            float p3 = (j0+col+1 > i0+fr1) ? 0.f : __expf(sacc[nt][3])*rlr1;
            uint32_t rel0 = swrel(fr0, (col*2) >> 4) + ((col*2) & 15);
            uint32_t rel1 = swrel(fr1, (col*2) >> 4) + ((col*2) & 15);
            *(uint32_t*)(smc + SM_PQHI + rel0) = bf2x(p0, p1);
            *(uint32_t*)(smc + SM_PQLO + rel0) = bf2x(bflo(p0), bflo(p1));
            *(uint32_t*)(smc + SM_PQHI + rel1) = bf2x(p2, p3);
            *(uint32_t*)(smc + SM_PQLO + rel1) = bf2x(bflo(p2), bflo(p3));
        }
        __syncthreads();

        // O += P V (3 split passes)
        #pragma unroll
        for (int kc = 0; kc < 4; kc++) {
            uint32_t ah[4], al[4], bh2[4], bl2[4], bh3[4], bl3[4];
            LDSM_X4(ah, sb + SM_PQHI + swrel(a_row, a_c16 + kc*2));
            LDSM_X4(al, sb + SM_PQLO + swrel(a_row, a_c16 + kc*2));
            LDSM_X4T(bh2, sb + SM_VHI + swrel(kc*16 + bv_row, bv_c16));
            LDSM_X4T(bl2, sb + SM_VLO + swrel(kc*16 + bv_row, bv_c16));
            LDSM_X4T(bh3, sb + SM_VHI + swrel(kc*16 + bv_row, bv_c16 + 2));
            LDSM_X4T(bl3, sb + SM_VLO + swrel(kc*16 + bv_row, bv_c16 + 2));
            #pragma unroll
            for (int nt = 0; nt < 4; nt++) {
                const uint32_t* BH = (nt < 2) ? bh2 : bh3;
                const uint32_t* BL = (nt < 2) ? bl2 : bl3;
                int u = (nt & 1)*2;
                MMA_BF16(oacc[nt], ah, BH[u], BH[u+1]);
                MMA_BF16(oacc[nt], ah, BL[u], BL[u+1]);
                MMA_BF16(oacc[nt], al, BH[u], BH[u+1]);
            }
        }

        // series (already normalized) + prior + sigma, streaming stores
        #pragma unroll
        for (int p = 0; p < 4; p++) {
            int rloc = srow + p*16;
            int irow = i0 + rloc;
            size_t off = ((size_t)bh*L_ + irow)*L_ + j0 + sc0;
            uint32_t rel = swrel(rloc, (sc0*2) >> 4) + ((sc0*2) & 15);
            uint2 hv = *(const uint2*)(smc + SM_PQHI + rel);
            uint2 lv = *(const uint2*)(smc + SM_PQLO + rel);
            float2 ha = bfup(hv.x), hb2 = bfup(hv.y);
            float2 la = bfup(lv.x), lb2 = bfup(lv.y);
            __stcs((float4*)(outS + off),
                   make_float4(ha.x+la.x, ha.y+la.y, hb2.x+lb2.x, hb2.y+lb2.y));
            // tile-strip underflow fast path for prior
            int dmin = j0 + sc0 > irow ? (j0 + sc0 - irow) : 0;
            int dfar = irow - (j0 + sc0 + 3);
            if (dfar > dmin) dmin = dfar;
            if (dmin < 0) dmin = 0;
            float dmin2 = (float)(dmin*dmin);
            if (dmin2 * i2s24[p] > 87.f) {
                __stcs((float4*)(outP + off), make_float4(0.f,0.f,0.f,0.f));
            } else {
                float vals[4];
                #pragma unroll
                for (int c = 0; c < 4; c++) {
                    int d = irow - (j0 + sc0 + c);
                    float arg = -(float)(d*d) * i2s24[p];
                    vals[c] = (arg > -87.f) ? (coef4[p] * __expf(arg)) : 0.f;
                }
                __stcs((float4*)(outP + off), make_float4(vals[0],vals[1],vals[2],vals[3]));
            }
            __stcs((float4*)(outG + off), make_float4(sig4[p],sig4[p],sig4[p],sig4[p]));
        }
    }

    // ---- V output (already normalized) ----
    {
        float* v0 = outV + (((size_t)(b*L_) + i0 + fr0)*H_ + h)*D_;
        float* v1 = outV + (((size_t)(b*L_) + i0 + fr1)*H_ + h)*D_;
        #pragma unroll
        for (int nt = 0; nt < 4; nt++) {
            int col = fcb + nt*8;
            __stcs((float2*)(v0 + col), make_float2(oacc[nt][0], oacc[nt][1]));
            __stcs((float2*)(v1 + col), make_float2(oacc[nt][2], oacc[nt][3]));
        }
    }
}

extern "C" void kernel_launch(void* const* d_in, const int* in_sizes, int n_in,
                              void* d_out, int out_size) {
    const float* q  = (const float*)d_in[0];
    const float* k  = (const float*)d_in[1];
    const float* v  = (const float*)d_in[2];
    const float* sg = (const float*)d_in[3];

    sigma_prep<<<(B_*H_*L_ + 255)/256, 256>>>(sg);
    split_prep<<<(B_*H_*L_*E_/4 + 255)/256, 256>>>(q, k, v);

    cudaFuncSetAttribute(attn_tc, cudaFuncAttributeMaxDynamicSharedMemorySize, SM_TOTAL);
    dim3 grid(B_*H_, NTILE);   // bh fastest; it = 31 - blockIdx.y (LPT)
    attn_tc<<<grid, 256, SM_TOTAL>>>((float*)d_out);
}